// round 2
// baseline (speedup 1.0000x reference)
#include <cuda_runtime.h>
#include <cstdint>

// Problem constants (fixed by the reference)
#define BB 64
#define NNA 256
#define EE 20
#define DD 25
#define VW_COLS 45   // ATOMEMB + DFEAT

// Scratch (allocation-free rule: __device__ globals)
__device__ float g_base [BB * NNA * EE];   // pre-tanh bias per (b,i,o): cfeat@Vw1^T + Vb
__device__ float g_cfeat[BB * NNA * EE];
__device__ float g_mask [BB * NNA];
__device__ float g_rowsum[BB * NNA];       // per-atom scalar u.tanh(c)
__device__ float g_uv[EE + 1];             // u[0..19], v at [20]

// ---------------- fast math helpers ----------------
__device__ __forceinline__ float ex2f(float x) {
    float y; asm("ex2.approx.f32 %0, %1;" : "=f"(y) : "f"(x)); return y;
}
__device__ __forceinline__ float rcpf(float x) {
    float y; asm("rcp.approx.f32 %0, %1;" : "=f"(y) : "f"(x)); return y;
}
// tanh(z) = 1 - 2/(e^{2z}+1); exact limits at +/-inf, ~1e-7 abs error
__device__ __forceinline__ float tanh_fast(float z) {
    float t = ex2f(z * 2.8853900817779268f);   // 2*log2(e)
    return fmaf(-2.0f, rcpf(t + 1.0f), 1.0f);
}

// ---------------- kernel A: fold top MLP ----------------
__global__ void k_uv(const float* __restrict__ W1, const float* __restrict__ b1,
                     const float* __restrict__ W2, const float* __restrict__ b2) {
    int o = threadIdx.x;
    if (o < EE) {
        float s = 0.0f;
        #pragma unroll
        for (int k = 0; k < 10; k++) s = fmaf(W2[k], W1[k * EE + o], s);
        g_uv[o] = s;
    } else if (o == EE) {
        float s = b2[0];
        #pragma unroll
        for (int k = 0; k < 10; k++) s = fmaf(W2[k], b1[k], s);
        g_uv[EE] = s;
    }
}

// ---------------- kernel B: per-row precompute ----------------
__global__ void k_pre(const int* __restrict__ z, const float* __restrict__ emb,
                      const float* __restrict__ Vw, const float* __restrict__ Vb) {
    int row = blockIdx.x * blockDim.x + threadIdx.x;
    if (row >= BB * NNA) return;
    int zi = z[row];
    float mk = (zi != 0) ? 1.0f : 0.0f;
    g_mask[row] = mk;
    float cf[EE];
    #pragma unroll
    for (int f = 0; f < EE; f++) {
        cf[f] = emb[zi * EE + f] * mk;
        g_cfeat[row * EE + f] = cf[f];
    }
    #pragma unroll
    for (int o = 0; o < EE; o++) {
        float s = Vb[o];
        #pragma unroll
        for (int f = 0; f < EE; f++) s = fmaf(cf[f], Vw[o * VW_COLS + f], s);
        g_base[row * EE + o] = s;
    }
}

// ---------------- kernel C: main pair loop ----------------
// One warp per (b,i) row. Lane owns 8 j's, processed 4 at a time (JU=4).
__global__ __launch_bounds__(128) void k_main(const float* __restrict__ dist,
                                              const float* __restrict__ Vw) {
    __shared__ float ws[DD][EE];   // ws[d][o] = Vw[o, 20+d]
    int tid = threadIdx.x;
    for (int t = tid; t < DD * EE; t += 128) {
        int d = t / EE, o = t % EE;
        ws[d][o] = Vw[o * VW_COLS + 20 + d];
    }
    __syncthreads();

    int warp = tid >> 5, lane = tid & 31;
    int row = blockIdx.x * 4 + warp;

    float acc[EE];
    #pragma unroll
    for (int o = 0; o < EE; o++) acc[o] = 0.0f;

    float mk = g_mask[row];
    if (mk != 0.0f) {
        float base[EE];
        #pragma unroll
        for (int o = 0; o < EE; o++) base[o] = __ldg(&g_base[row * EE + o]);

        const float* drow = dist + (size_t)row * NNA;

        #pragma unroll
        for (int pass = 0; pass < 2; pass++) {
            float x[4], rk[4], p[4];
            float m[4][EE];
            #pragma unroll
            for (int q = 0; q < 4; q++)
                x[q] = __ldg(&drow[lane + 32 * q + 128 * pass]);
            #pragma unroll
            for (int q = 0; q < 4; q++) {
                // rk = e^{0.8x} * e^{-0.08};  p0 = e^{-2x^2}
                rk[q] = ex2f(x[q] * 1.1541560327111707f) * 0.9231163463866358f;
                p[q]  = ex2f(x[q] * x[q] * -2.8853900817779268f);
                #pragma unroll
                for (int o = 0; o < EE; o++) m[q][o] = base[o];
            }
            #pragma unroll
            for (int d = 0; d < DD; d++) {
                #pragma unroll
                for (int o = 0; o < EE; o++) {
                    float w = ws[d][o];
                    #pragma unroll
                    for (int q = 0; q < 4; q++)
                        m[q][o] = fmaf(p[q], w, m[q][o]);
                }
                #pragma unroll
                for (int q = 0; q < 4; q++) {
                    p[q]  = p[q] * rk[q];
                    rk[q] = rk[q] * 0.8521437889662113f;   // e^{-0.16}, immediate
                }
            }
            #pragma unroll
            for (int q = 0; q < 4; q++)
                #pragma unroll
                for (int o = 0; o < EE; o++)
                    acc[o] += tanh_fast(m[q][o]);
        }
    }

    // deterministic warp butterfly reduce of acc[o]
    #pragma unroll
    for (int o = 0; o < EE; o++) {
        float v = acc[o];
        #pragma unroll
        for (int off = 16; off > 0; off >>= 1)
            v += __shfl_xor_sync(0xffffffffu, v, off);
        acc[o] = v;
    }

    if (lane == 0) {
        float s = 0.0f;
        if (mk != 0.0f) {
            #pragma unroll
            for (int o = 0; o < EE; o++) {
                float c = g_cfeat[row * EE + o] + acc[o];
                s = fmaf(g_uv[o], tanh_fast(c), s);
            }
        }
        g_rowsum[row] = s;
    }
}

// ---------------- kernel D: final deterministic reduce ----------------
__global__ void k_final(float* __restrict__ out) {
    __shared__ float red[NNA];
    int b = blockIdx.x, t = threadIdx.x;
    red[t] = g_rowsum[b * NNA + t];
    __syncthreads();
    #pragma unroll
    for (int s = NNA / 2; s > 0; s >>= 1) {
        if (t < s) red[t] += red[t + s];
        __syncthreads();
    }
    if (t == 0) out[b] = red[0] + (float)NNA * g_uv[EE];
}

// ---------------- launcher ----------------
extern "C" void kernel_launch(void* const* d_in, const int* in_sizes, int n_in,
                              void* d_out, int out_size) {
    const int*   z    = (const int*)  d_in[0];
    const float* dist = (const float*)d_in[1];
    const float* emb  = (const float*)d_in[2];
    const float* Vw   = (const float*)d_in[3];
    const float* Vb   = (const float*)d_in[4];
    const float* W1   = (const float*)d_in[5];
    const float* b1   = (const float*)d_in[6];
    const float* W2   = (const float*)d_in[7];
    const float* b2   = (const float*)d_in[8];
    float* out = (float*)d_out;

    k_uv  <<<1, 32>>>(W1, b1, W2, b2);
    k_pre <<<(BB * NNA + 255) / 256, 256>>>(z, emb, Vw, Vb);
    k_main<<<BB * NNA / 4, 128>>>(dist, Vw);
    k_final<<<BB, NNA>>>(out);
}

// round 3
// speedup vs baseline: 20.5484x; 20.5484x over previous
#include <cuda_runtime.h>
#include <cstdint>

#define BB 64
#define NNA 256
#define EE 20
#define DD 25
#define VW_COLS 45   // ATOMEMB + DFEAT

// scratch (__device__ globals per allocation-free rule)
__device__ float g_rowsum[BB * NNA];   // per-atom u . tanh(c)

// ---------------- fast math ----------------
__device__ __forceinline__ float ex2f(float x) {
    float y; asm("ex2.approx.f32 %0, %1;" : "=f"(y) : "f"(x)); return y;
}
__device__ __forceinline__ float rcpf(float x) {
    float y; asm("rcp.approx.f32 %0, %1;" : "=f"(y) : "f"(x)); return y;
}
// tanh(z) = 1 - 2/(e^{2z}+1)
__device__ __forceinline__ float tanh_fast(float z) {
    float t = ex2f(z * 2.8853900817779268f);   // 2*log2(e)
    return fmaf(-2.0f, rcpf(t + 1.0f), 1.0f);
}

// ---------------- main kernel: one warp per (b,i) row ----------------
// 8 warps (8 rows) per 256-thread block.
__global__ __launch_bounds__(256) void k_main(const int* __restrict__ z,
                                              const float* __restrict__ dist,
                                              const float* __restrict__ emb,
                                              const float* __restrict__ Vw,
                                              const float* __restrict__ Vb,
                                              const float* __restrict__ W1,
                                              const float* __restrict__ W2) {
    __shared__ float  ws1[EE][EE];     // ws1[o][f] = Vw[o, f]         (f < 20)
    __shared__ float2 ws2[EE][13];     // ws2[o][dp] = (Vw[o,20+2dp], Vw[o,20+2dp+1] or 0)
    __shared__ float  us[EE];          // u[o] = sum_k W2[k] * W1[k][o]

    int tid = threadIdx.x;
    for (int t = tid; t < EE * EE; t += 256) {
        int o = t / EE, f = t % EE;
        ws1[o][f] = Vw[o * VW_COLS + f];
    }
    for (int t = tid; t < EE * 13; t += 256) {
        int o = t / 13, dp = t % 13;
        float a = Vw[o * VW_COLS + 20 + 2 * dp];
        float b = (2 * dp + 1 < DD) ? Vw[o * VW_COLS + 20 + 2 * dp + 1] : 0.0f;
        ws2[o][dp] = make_float2(a, b);
    }
    if (tid < EE) {
        float s = 0.0f;
        #pragma unroll
        for (int k = 0; k < 10; k++) s = fmaf(W2[k], W1[k * EE + tid], s);
        us[tid] = s;
    }
    __syncthreads();

    int warp = tid >> 5, lane = tid & 31;
    int row = blockIdx.x * 8 + warp;

    int   zi = z[row];
    float mk = (zi != 0) ? 1.0f : 0.0f;

    // acc starts at cfeat; accumulates agg; ends as c
    float acc[EE];
    #pragma unroll
    for (int o = 0; o < EE; o++) acc[o] = emb[zi * EE + o] * mk;

    if (mk != 0.0f) {
        // base[o] = Vb[o] + cfeat . Vw[o, :20]   (redundant per lane; cheap)
        float base[EE];
        #pragma unroll
        for (int o = 0; o < EE; o++) {
            float s = Vb[o];
            #pragma unroll
            for (int f = 0; f < EE; f++) s = fmaf(acc[f], ws1[o][f], s);
            base[o] = s;
        }

        const float* drow = dist + (size_t)row * NNA;

        #pragma unroll 1
        for (int it = 0; it < 4; it++) {
            float x0 = __ldg(&drow[lane + 64 * it]);
            float x1 = __ldg(&drow[lane + 64 * it + 32]);

            // p_d = exp(-2 (x - 0.2 d)^2) via geometric recurrence; p[25] = 0 pad
            float p0[DD + 1], p1[DD + 1];
            float rk0 = ex2f(x0 * 1.1541560327111707f) * 0.9231163463866358f; // e^{0.8x-0.08}
            float rk1 = ex2f(x1 * 1.1541560327111707f) * 0.9231163463866358f;
            p0[0] = ex2f(x0 * x0 * -2.8853900817779268f);                     // e^{-2x^2}
            p1[0] = ex2f(x1 * x1 * -2.8853900817779268f);
            #pragma unroll
            for (int d = 0; d < DD - 1; d++) {
                p0[d + 1] = p0[d] * rk0;
                p1[d + 1] = p1[d] * rk1;
                rk0 *= 0.8521437889662113f;    // e^{-0.16} (immediate)
                rk1 *= 0.8521437889662113f;
            }
            p0[DD] = 0.0f; p1[DD] = 0.0f;

            #pragma unroll
            for (int o = 0; o < EE; o++) {
                float m0 = base[o], m1 = base[o];
                #pragma unroll
                for (int dp = 0; dp < 13; dp++) {
                    float2 w = ws2[o][dp];
                    m0 = fmaf(p0[2 * dp],     w.x, m0);
                    m0 = fmaf(p0[2 * dp + 1], w.y, m0);
                    m1 = fmaf(p1[2 * dp],     w.x, m1);
                    m1 = fmaf(p1[2 * dp + 1], w.y, m1);
                }
                acc[o] += tanh_fast(m0) + tanh_fast(m1);
            }
        }
    }

    // deterministic warp butterfly reduce (acc now holds c per-lane partials)
    #pragma unroll
    for (int o = 0; o < EE; o++) {
        float v = acc[o];
        #pragma unroll
        for (int off = 16; off > 0; off >>= 1)
            v += __shfl_xor_sync(0xffffffffu, v, off);
        acc[o] = v;
    }

    if (lane == 0) {
        float s = 0.0f;
        if (mk != 0.0f) {
            // note: butterfly summed cfeat 32x; rescale. cfeat entered acc in
            // every lane identically, agg parts once each. Correct c:
            //   c[o] = cfeat[o] + agg[o] = acc[o] - 31*cfeat[o]
            #pragma unroll
            for (int o = 0; o < EE; o++) {
                float cf = emb[zi * EE + o];   // mk==1 here
                float c  = acc[o] - 31.0f * cf;
                s = fmaf(us[o], tanh_fast(c), s);
            }
        }
        g_rowsum[row] = s;
    }
}

// ---------------- final deterministic reduce ----------------
__global__ void k_final(const float* __restrict__ W2, const float* __restrict__ b1,
                        const float* __restrict__ b2, float* __restrict__ out) {
    __shared__ float red[NNA];
    int b = blockIdx.x, t = threadIdx.x;
    red[t] = g_rowsum[b * NNA + t];
    __syncthreads();
    #pragma unroll
    for (int s = NNA / 2; s > 0; s >>= 1) {
        if (t < s) red[t] += red[t + s];
        __syncthreads();
    }
    if (t == 0) {
        float v = b2[0];
        #pragma unroll
        for (int k = 0; k < 10; k++) v = fmaf(W2[k], b1[k], v);
        out[b] = red[0] + (float)NNA * v;
    }
}

// ---------------- launcher ----------------
extern "C" void kernel_launch(void* const* d_in, const int* in_sizes, int n_in,
                              void* d_out, int out_size) {
    const int*   z    = (const int*)  d_in[0];
    const float* dist = (const float*)d_in[1];
    const float* emb  = (const float*)d_in[2];
    const float* Vw   = (const float*)d_in[3];
    const float* Vb   = (const float*)d_in[4];
    const float* W1   = (const float*)d_in[5];
    const float* b1   = (const float*)d_in[6];
    const float* W2   = (const float*)d_in[7];
    const float* b2   = (const float*)d_in[8];
    float* out = (float*)d_out;

    k_main <<<BB * NNA / 8, 256>>>(z, dist, emb, Vw, Vb, W1, W2);
    k_final<<<BB, NNA>>>(W2, b1, b2, out);
}

// round 5
// speedup vs baseline: 20.9061x; 1.0174x over previous
#include <cuda_runtime.h>
#include <cstdint>

#define BB 64
#define NNA 256
#define EE 20
#define DD 25
#define VW_COLS 45   // ATOMEMB + DFEAT

typedef unsigned long long ull;

// scratch (__device__ globals per allocation-free rule)
__device__ float g_rowsum[BB * NNA];

// ---------------- fast math ----------------
__device__ __forceinline__ float ex2f(float x) {
    float y; asm("ex2.approx.f32 %0, %1;" : "=f"(y) : "f"(x)); return y;
}
__device__ __forceinline__ float rcpf(float x) {
    float y; asm("rcp.approx.f32 %0, %1;" : "=f"(y) : "f"(x)); return y;
}
__device__ __forceinline__ float tanh_fast(float z) {
    float t = ex2f(z * 2.8853900817779268f);   // 2*log2(e)
    return fmaf(-2.0f, rcpf(t + 1.0f), 1.0f);
}
// ---------------- packed f32x2 ----------------
__device__ __forceinline__ ull pack2(float lo, float hi) {
    ull r; asm("mov.b64 %0, {%1, %2};" : "=l"(r) : "f"(lo), "f"(hi)); return r;
}
__device__ __forceinline__ void unpack2(ull v, float& lo, float& hi) {
    asm("mov.b64 {%0, %1}, %2;" : "=f"(lo), "=f"(hi) : "l"(v));
}
__device__ __forceinline__ ull ffma2(ull a, ull b, ull c) {
    ull d; asm("fma.rn.f32x2 %0, %1, %2, %3;" : "=l"(d) : "l"(a), "l"(b), "l"(c)); return d;
}
__device__ __forceinline__ ull fmul2(ull a, ull b) {
    ull d; asm("mul.rn.f32x2 %0, %1, %2;" : "=l"(d) : "l"(a), "l"(b)); return d;
}

// ---------------- main kernel: one warp per (b,i) row, 8 rows/block ----------------
__global__ __launch_bounds__(256, 2) void k_main(const int* __restrict__ z,
                                                 const float* __restrict__ dist,
                                                 const float* __restrict__ emb,
                                                 const float* __restrict__ Vw,
                                                 const float* __restrict__ Vb,
                                                 const float* __restrict__ W1,
                                                 const float* __restrict__ W2) {
    __shared__ float      ws1[EE][EE];   // Vw[o, f] for f<20
    __shared__ ulonglong2 wsx[EE][13];   // {(w2d,w2d),(w2d+1,w2d+1)} duplicated pairs
    __shared__ float      us[EE];        // u = W2 @ W1

    int tid = threadIdx.x;
    for (int t = tid; t < EE * EE; t += 256) {
        int o = t / EE, f = t % EE;
        ws1[o][f] = Vw[o * VW_COLS + f];
    }
    for (int t = tid; t < EE * 13; t += 256) {
        int o = t / 13, dp = t % 13;
        float a = Vw[o * VW_COLS + 20 + 2 * dp];
        float b = (2 * dp + 1 < DD) ? Vw[o * VW_COLS + 20 + 2 * dp + 1] : 0.0f;
        wsx[o][dp].x = pack2(a, a);
        wsx[o][dp].y = pack2(b, b);
    }
    if (tid < EE) {
        float s = 0.0f;
        #pragma unroll
        for (int k = 0; k < 10; k++) s = fmaf(W2[k], W1[k * EE + tid], s);
        us[tid] = s;
    }
    __syncthreads();

    int warp = tid >> 5, lane = tid & 31;
    int row = blockIdx.x * 8 + warp;

    int   zi = z[row];
    float mk = (zi != 0) ? 1.0f : 0.0f;

    // acc starts at cfeat; accumulates agg over this lane's j's
    float acc[EE];
    #pragma unroll
    for (int o = 0; o < EE; o++) acc[o] = emb[zi * EE + o] * mk;

    if (mk != 0.0f) {
        float base[EE];
        #pragma unroll
        for (int o = 0; o < EE; o++) {
            float s = Vb[o];
            #pragma unroll
            for (int f = 0; f < EE; f++) s = fmaf(acc[f], ws1[o][f], s);
            base[o] = s;
        }

        const float2* drow2 = (const float2*)(dist + (size_t)row * NNA);
        const ull decay2 = pack2(0.8521437889662113f, 0.8521437889662113f); // e^{-0.16}

        #pragma unroll 1
        for (int it = 0; it < 4; it++) {
            float2 x2 = __ldg(&drow2[lane + 32 * it]);   // j = 2*(lane+32it), +1
            float x0 = x2.x, x1 = x2.y;

            // packed RBF: p_d = exp(-2 (x - 0.2 d)^2), geometric recurrence
            ull pp[DD + 1];
            float rk0 = ex2f(x0 * 1.1541560327111707f) * 0.9231163463866358f; // e^{0.8x-0.08}
            float rk1 = ex2f(x1 * 1.1541560327111707f) * 0.9231163463866358f;
            float p00 = ex2f(x0 * x0 * -2.8853900817779268f);                 // e^{-2x^2}
            float p10 = ex2f(x1 * x1 * -2.8853900817779268f);
            ull rk = pack2(rk0, rk1);
            pp[0] = pack2(p00, p10);
            #pragma unroll
            for (int d = 0; d < DD; d++) {
                pp[d + 1] = fmul2(pp[d], rk);
                rk = fmul2(rk, decay2);
            }
            // (pp[25] real but its weight pad is 0)

            #pragma unroll
            for (int o = 0; o < EE; o++) {
                ull m = pack2(base[o], base[o]);
                #pragma unroll
                for (int dp = 0; dp < 13; dp++) {
                    ulonglong2 w = wsx[o][dp];
                    m = ffma2(pp[2 * dp],     w.x, m);
                    m = ffma2(pp[2 * dp + 1], w.y, m);
                }
                float m0, m1; unpack2(m, m0, m1);
                acc[o] += tanh_fast(m0) + tanh_fast(m1);
            }
        }
    }

    // deterministic warp butterfly reduce
    #pragma unroll
    for (int o = 0; o < EE; o++) {
        float v = acc[o];
        #pragma unroll
        for (int off = 16; off > 0; off >>= 1)
            v += __shfl_xor_sync(0xffffffffu, v, off);
        acc[o] = v;
    }

    if (lane == 0) {
        float s = 0.0f;
        if (mk != 0.0f) {
            // cfeat entered acc identically in all 32 lanes; correct: c = acc - 31*cfeat
            #pragma unroll
            for (int o = 0; o < EE; o++) {
                float cf = emb[zi * EE + o];
                float c  = acc[o] - 31.0f * cf;
                s = fmaf(us[o], tanh_fast(c), s);
            }
        }
        g_rowsum[row] = s;
    }
}

// ---------------- final deterministic reduce ----------------
__global__ void k_final(const float* __restrict__ W2, const float* __restrict__ b1,
                        const float* __restrict__ b2, float* __restrict__ out) {
    __shared__ float red[NNA];
    int b = blockIdx.x, t = threadIdx.x;
    red[t] = g_rowsum[b * NNA + t];
    __syncthreads();
    #pragma unroll
    for (int s = NNA / 2; s > 0; s >>= 1) {
        if (t < s) red[t] += red[t + s];
        __syncthreads();
    }
    if (t == 0) {
        float v = b2[0];
        #pragma unroll
        for (int k = 0; k < 10; k++) v = fmaf(W2[k], b1[k], v);
        out[b] = red[0] + (float)NNA * v;
    }
}

// ---------------- launcher ----------------
extern "C" void kernel_launch(void* const* d_in, const int* in_sizes, int n_in,
                              void* d_out, int out_size) {
    const int*   z    = (const int*)  d_in[0];
    const float* dist = (const float*)d_in[1];
    const float* emb  = (const float*)d_in[2];
    const float* Vw   = (const float*)d_in[3];
    const float* Vb   = (const float*)d_in[4];
    const float* W1   = (const float*)d_in[5];
    const float* b1   = (const float*)d_in[6];
    const float* W2   = (const float*)d_in[7];
    const float* b2   = (const float*)d_in[8];
    float* out = (float*)d_out;

    k_main <<<BB * NNA / 8, 256>>>(z, dist, emb, Vw, Vb, W1, W2);
    k_final<<<BB, NNA>>>(W2, b1, b2, out);
}